// round 12
// baseline (speedup 1.0000x reference)
#include <cuda_runtime.h>
#include <cstdint>

// Delta modulation encoder: 512 independent serial scans of length 131072.
// Bit-exact fp32 replication of:
//   err = fl(x_t - r); p = err>0.1; n = err<-0.1; spike = p-n; r = fl(r + spike*0.1)
//
// R11 lesson: chain-latency-bound at ~21-23 cyc (FSETP pred production = 13 cyc).
// R12: predicate-free chain, proven bit-exact in R7, now without PTX-asm mov
// pollution (C++ reinterpret intrinsics; LOP3 via xor-and-xor pattern):
//   mu = FFMA(e, -2^127, 0.1*2^127)  -> sign(0.1 - e), +0 iff e == 0.1
//   md = FFMA(e, +2^127, 0.1*2^127)  -> sign(0.1 + e), +0 iff e == -0.1
//   su = mu >> 31, sd = md >> 31 (arith) -> {0, -1} masks, ties exact
//   err' = LOP3-select(Eu, Ed, Ez; su, sd)
// Chain: FFMA(4) -> SHF(4) -> LOP3(4) -> LOP3(4) = 16 cyc/step, no predicates.
// Spike conversion offloaded to the I/O warp (stores carried err, R11 scheme).

constexpr int T_LEN = 131072;
constexpr int NSEQ  = 512;            // 64 * 8
constexpr int SEQ_B = 4;              // sequences (rows) per block, one per compute warp
constexpr int TILE  = 128;            // time steps per lane per tile
constexpr int NT    = T_LEN / TILE;   // 1024 tiles
constexpr int ROWF  = TILE + 4;       // 132 floats = 528B stride
constexpr int NBUF  = 3;              // input ring: t, t+1 resident, t+2 in flight
constexpr int GRP   = TILE / 4;       // 32 float4 groups per tile
constexpr int NTHREADS = 160;         // 4 compute warps + 1 I/O warp

struct DMCarry {
    uint32_t rr;            // recon bits
    uint32_t cu, cd;        // bits of fl(rr+0.1f), fl(rr-0.1f)
    uint32_t Eu, Ed, Ez;    // bits of x_{t+1} - {cu, cd, rr}
};

__device__ __forceinline__ uint32_t bitsel(uint32_t z, uint32_t d, uint32_t m) {
    return z ^ ((z ^ d) & m);          // m ? d : z   (one LOP3)
}

// One element. e = err_t bits (input), xnn = x[t+2]. Returns err_{t+1} bits.
// Bit-exact (sign-FFMA guard validated in R7). 13 ops, no predicates, no movs.
__device__ __forceinline__ uint32_t dm_step(uint32_t e, DMCarry& s, float xnn) {
    const float BIG = __uint_as_float(0x7F000000u);   // 2^127
    const float THB = __uint_as_float(0x7D4CCCCDu);   // 0.1f * 2^127

    const float ef = __uint_as_float(e);
    const float mu = __fmaf_rn(ef, -BIG, THB);        // sign(0.1 - e)
    const float md = __fmaf_rn(ef,  BIG, THB);        // sign(0.1 + e)
    const uint32_t su = (uint32_t)((int32_t)__float_as_uint(mu) >> 31); // -1 iff e>0.1
    const uint32_t sd = (uint32_t)((int32_t)__float_as_uint(md) >> 31); // -1 iff e<-0.1

    // err' = su ? Eu : (sd ? Ed : Ez)        [chain: 2 LOP3]
    const uint32_t en = bitsel(bitsel(s.Ez, s.Ed, sd), s.Eu, su);
    // rr'  = su ? cu : (sd ? cd : rr)        [off-chain: 2 LOP3]
    const uint32_t rn = bitsel(bitsel(s.rr, s.cd, sd), s.cu, su);

    const float rrf = __uint_as_float(rn);
    const float cuf = rrf + 0.1f;                     // fl(rr' + 0.1f)
    const float cdf = rrf - 0.1f;                     // fl(rr' - 0.1f)
    s.rr = rn;
    s.cu = __float_as_uint(cuf);
    s.cd = __float_as_uint(cdf);
    s.Eu = __float_as_uint(xnn - cuf);
    s.Ed = __float_as_uint(xnn - cdf);
    s.Ez = __float_as_uint(xnn - rrf);
    return en;
}

__device__ __forceinline__ void cp_async16(uint32_t dst_smem, const void* src) {
    asm volatile("cp.async.cg.shared.global [%0], [%1], 16;"
                 :: "r"(dst_smem), "l"(src));
}
__device__ __forceinline__ void cp_commit() {
    asm volatile("cp.async.commit_group;" ::: "memory");
}
__device__ __forceinline__ void cp_wait1() {
    asm volatile("cp.async.wait_group 1;" ::: "memory");
}
__device__ __forceinline__ void bar1() {
    asm volatile("bar.sync 1, %0;" :: "n"(NTHREADS) : "memory");
}
__device__ __forceinline__ void bar2() {
    asm volatile("bar.sync 2, %0;" :: "n"(NTHREADS) : "memory");
}

__global__ __launch_bounds__(NTHREADS, 1)
void DeltaModulationEncoder_kernel(const float* __restrict__ x,
                                   float* __restrict__ out) {
    __shared__ __align__(16) float sin_buf[NBUF][SEQ_B * ROWF];  // input ring
    __shared__ __align__(16) float serr[2][SEQ_B * ROWF];        // err staging

    const int tid  = threadIdx.x;
    const int warp = tid >> 5;
    const int lane = tid & 31;
    const int seqbase = blockIdx.x * SEQ_B;

    if (warp == 4) {
        // ───────────────────────── I/O warp ─────────────────────────
        const size_t rowstride = (size_t)T_LEN * 4;
        const char* gsrc = (const char*)(x + (size_t)seqbase * T_LEN) + lane * 16;
        char*       gdst = (char*)(out + (size_t)seqbase * T_LEN) + lane * 16;

        uint32_t sin_addr[NBUF];
#pragma unroll
        for (int b = 0; b < NBUF; b++)
            sin_addr[b] = (uint32_t)__cvta_generic_to_shared(&sin_buf[b][0])
                        + (uint32_t)(lane * 16);

        // Convert err tile -> spikes (exact: +-1.0f / +0.0f), STG directly.
        auto flush_tile = [&](int tp) {
            const float* sb = &serr[tp & 1][0] + lane * 4;
            char* g = gdst + (size_t)tp * TILE * 4;
#pragma unroll
            for (int i = 0; i < SEQ_B; i++) {
                float4 e = *(const float4*)(sb + i * ROWF);
                float4 sp;
                sp.x = (e.x > 0.1f) ? 1.0f : ((e.x < -0.1f) ? -1.0f : 0.0f);
                sp.y = (e.y > 0.1f) ? 1.0f : ((e.y < -0.1f) ? -1.0f : 0.0f);
                sp.z = (e.z > 0.1f) ? 1.0f : ((e.z < -0.1f) ? -1.0f : 0.0f);
                sp.w = (e.w > 0.1f) ? 1.0f : ((e.w < -0.1f) ? -1.0f : 0.0f);
                *(float4*)(g + (size_t)i * rowstride) = sp;
            }
        };

#pragma unroll
        for (int t0 = 0; t0 < 2; t0++) {
            const char* g = gsrc + (size_t)t0 * TILE * 4;
            const uint32_t s = sin_addr[t0];
#pragma unroll
            for (int i = 0; i < SEQ_B; i++)
                cp_async16(s + (uint32_t)(i * ROWF * 4), g + (size_t)i * rowstride);
            cp_commit();
        }

        int slot_w = 2;
        for (int t = 0; t < NT; ++t) {
            if (t + 2 < NT) {
                const char* g = gsrc + (size_t)(t + 2) * TILE * 4;
                const uint32_t s = sin_addr[slot_w];
#pragma unroll
                for (int i = 0; i < SEQ_B; i++)
                    cp_async16(s + (uint32_t)(i * ROWF * 4), g + (size_t)i * rowstride);
            }
            cp_commit();
            cp_wait1();                 // tiles t, t+1 resident
            bar1();                     // release compute for tile t

            if (t > 0) flush_tile(t - 1);

            bar2();                     // serr[(t-1)&1] reusable; tile t errs visible
            slot_w = (slot_w + 1 == NBUF) ? 0 : slot_w + 1;
        }
        flush_tile(NT - 1);
    } else {
        // ──────────────────── compute warps 0-3, 1 seq each ────────────────────
        const int row = warp;
        const bool writer = (lane == 0);

        DMCarry st;
        uint32_t e;
        int s0 = 0;
        for (int t = 0; t < NT; ++t) {
            const int s1 = (s0 + 1 == NBUF) ? 0 : s0 + 1;
            bar1();                     // tiles t (slot s0), t+1 (slot s1) resident

            if (t == 0) {               // recon r0 = +0
                const float x0 = sin_buf[0][row * ROWF + 0];
                const float x1 = sin_buf[0][row * ROWF + 1];
                e      = __float_as_uint(x0);          // err_0 = fl(x0 - 0)
                st.rr  = 0u;                           // +0.0f
                st.cu  = 0x3DCCCCCDu;                  //  0.1f
                st.cd  = 0xBDCCCCCDu;                  // -0.1f
                st.Eu  = __float_as_uint(x1 - 0.1f);
                st.Ed  = __float_as_uint(x1 + 0.1f);
                st.Ez  = __float_as_uint(x1);
            }

            const float4* bk  = (const float4*)(&sin_buf[s0][0] + row * ROWF);
            const float4* bk1 = (const float4*)(&sin_buf[s1][0] + row * ROWF);
            uint4* so = (uint4*)(&serr[t & 1][0] + row * ROWF);

            float4 cur = bk[0];
            float4 nxt = bk[1];
#pragma unroll
            for (int g = 0; g < GRP; ++g) {
                // group g+2 (peeks into tile t+1 for g >= GRP-2; past the last
                // tile this is stale smem feeding only never-output candidates)
                const float4 nn = (g < GRP - 2) ? bk[g + 2] : bk1[g - (GRP - 2)];

                uint4 ev;                        // err_t bits (outputs)
                ev.x = e; e = dm_step(e, st, cur.z);
                ev.y = e; e = dm_step(e, st, cur.w);
                ev.z = e; e = dm_step(e, st, nxt.x);
                ev.w = e; e = dm_step(e, st, nxt.y);
                if (writer) so[g] = ev;          // predicated STS.128, lane 0

                cur = nxt;
                nxt = nn;
            }
            bar2();                     // hand serr[t&1] to the I/O warp
            s0 = s1;
        }
    }
}

extern "C" void kernel_launch(void* const* d_in, const int* in_sizes, int n_in,
                              void* d_out, int out_size) {
    (void)in_sizes; (void)n_in; (void)out_size;
    const float* x = (const float*)d_in[0];
    float* out     = (float*)d_out;

    // 128 blocks x (4 compute warps + 1 I/O warp), 1 sequence per compute warp.
    DeltaModulationEncoder_kernel<<<NSEQ / SEQ_B, NTHREADS>>>(x, out);
}

// round 13
// speedup vs baseline: 1.1251x; 1.1251x over previous
#include <cuda_runtime.h>
#include <cstdint>

// Delta modulation encoder: 512 independent serial scans of length 131072.
// Bit-exact fp32 replication of:
//   err = fl(x_t - r); p = err>0.1; n = err<-0.1; spike = p-n; r = fl(r + spike*0.1)
//
// R12 lesson: fp-result -> int-pipe consumption costs ~13 cyc (same class as
// predicate production), so every exact chain formulation floors at ~21-23
// cyc/step. R13 removes the remaining overhead instead: NO warp
// specialization, NO barriers. Each warp owns one sequence end-to-end:
//   - 32 lanes cooperatively cp.async the warp's own 512B tile row (1 instr)
//   - per-warp cp.async.wait_group (program-ordered ring, NBUF=3, race-free)
//   - lane 0 STGs spike float4s directly to global (no staging smem)
// dm_step is the R6 12-op integrated form (best measured, bit-exact).

constexpr int T_LEN = 131072;
constexpr int NSEQ  = 512;            // 64 * 8
constexpr int WARPS = 4;              // warps per block, one sequence each
constexpr int TILE  = 128;            // time steps per tile
constexpr int NT    = T_LEN / TILE;   // 1024 tiles
constexpr int NBUF  = 3;              // ring: t, t+1 resident, t+2 in flight
constexpr int GRP   = TILE / 4;       // 32 float4 groups per tile

struct DMState {
    float err;              // resolved err_t (chain state)
    float rr;               // resolved recon
    float Eu, Ed, Ez;       // x_{t+1} - {fl(rr+0.1), fl(rr-0.1), rr}
};

// One element. xnn = x[t+2]. Returns spike_t in {-1,0,1}. Bit-exact.
__device__ __forceinline__ float dm_step(DMState& s, float xnn) {
    float spike;
    asm("{\n\t"
        ".reg .pred p, n;\n\t"
        ".reg .f32  t0, t1, cu, cd;\n\t"
        "setp.gt.f32 p, %1, 0f3DCCCCCD;\n\t"            // err >  0.1f
        "setp.lt.f32 n, %1, 0fBDCCCCCD;\n\t"            // err < -0.1f
        "selp.f32 t0, 0fBF800000, 0f00000000, n;\n\t"   // n ? -1 : 0
        "selp.f32 %0, 0f3F800000, t0, p;\n\t"           // spike
        "selp.f32 t1, %4, %5, n;\n\t"                   // n ? Ed : Ez
        "selp.f32 %1, %3, t1, p;\n\t"                   // err' (chain)
        "fma.rn.f32 %2, %0, 0f3DCCCCCD, %2;\n\t"        // rr' = fl(rr + spike*0.1f)
        "add.f32  cu, %2, 0f3DCCCCCD;\n\t"              // fl(rr'+0.1f)
        "add.f32  cd, %2, 0fBDCCCCCD;\n\t"              // fl(rr'-0.1f)
        "sub.f32  %3, %6, cu;\n\t"                      // Eu'
        "sub.f32  %4, %6, cd;\n\t"                      // Ed'
        "sub.f32  %5, %6, %2;\n\t"                      // Ez'
        "}"
        : "=f"(spike),
          "+f"(s.err), "+f"(s.rr),
          "+f"(s.Eu), "+f"(s.Ed), "+f"(s.Ez)
        : "f"(xnn));
    return spike;
}

__device__ __forceinline__ void cp_async16(uint32_t dst_smem, const void* src) {
    asm volatile("cp.async.cg.shared.global [%0], [%1], 16;"
                 :: "r"(dst_smem), "l"(src));
}
__device__ __forceinline__ void cp_commit() {
    asm volatile("cp.async.commit_group;" ::: "memory");
}
__device__ __forceinline__ void cp_wait1() {
    asm volatile("cp.async.wait_group 1;" ::: "memory");
}

__global__ __launch_bounds__(WARPS * 32, 1)
void DeltaModulationEncoder_kernel(const float* __restrict__ x,
                                   float* __restrict__ out) {
    // Per-warp private ring: 3 slots x 512B. 4 warps -> 6 KB.
    __shared__ __align__(16) float sin_buf[WARPS][NBUF][TILE];

    const int warp = threadIdx.x >> 5;
    const int lane = threadIdx.x & 31;
    const int seq  = blockIdx.x * WARPS + warp;

    const char* gsrc = (const char*)(x + (size_t)seq * T_LEN) + lane * 16;
    char*       gdst = (char*)(out + (size_t)seq * T_LEN);

    uint32_t slot[NBUF];
#pragma unroll
    for (int b = 0; b < NBUF; b++)
        slot[b] = (uint32_t)__cvta_generic_to_shared(&sin_buf[warp][b][0])
                + (uint32_t)(lane * 16);

    // Prologue: tiles 0 and 1 in flight; wait for tile 0; init state.
    cp_async16(slot[0], gsrc);
    cp_commit();
    cp_async16(slot[1], gsrc + (size_t)TILE * 4);
    cp_commit();
    cp_wait1();                     // slot0 resident
    __syncwarp();

    DMState st;
    {
        const float x0 = sin_buf[warp][0][0];
        const float x1 = sin_buf[warp][0][1];
        st.err = x0;                // fl(x0 - 0)
        st.rr  = 0.0f;
        st.Eu  = x1 - 0.1f;         // fl(x1 - fl(0+0.1))
        st.Ed  = x1 + 0.1f;         // fl(x1 - fl(0-0.1))
        st.Ez  = x1;                // fl(x1 - 0)
    }

    int s0 = 0;
    for (int t = 0; t < NT; ++t) {
        const int s1 = (s0 + 1 == NBUF) ? 0 : s0 + 1;
        const int s2 = (s1 + 1 == NBUF) ? 0 : s1 + 1;   // ring slot for t+2

        // Program order guarantees slot s2 (== slot of t-1) is done being read.
        if (t + 2 < NT)
            cp_async16(slot[s2], gsrc + (size_t)(t + 2) * TILE * 4);
        cp_commit();                // empty groups fine near the tail
        cp_wait1();                 // <=1 pending -> tiles t, t+1 resident
        __syncwarp();

        const float4* bk  = (const float4*)&sin_buf[warp][s0][0];
        const float4* bk1 = (const float4*)&sin_buf[warp][s1][0];
        char* gd = gdst + (size_t)t * TILE * 4;

        float4 cur = bk[0];
        float4 nxt = bk[1];
#pragma unroll
        for (int g = 0; g < GRP; ++g) {
            // group g+2 (peeks into tile t+1 for g >= GRP-2; past the last
            // tile this reads stale smem feeding only never-output candidates)
            const float4 nn = (g < GRP - 2) ? bk[g + 2] : bk1[g - (GRP - 2)];

            float4 sp;
            sp.x = dm_step(st, cur.z);
            sp.y = dm_step(st, cur.w);
            sp.z = dm_step(st, nxt.x);
            sp.w = dm_step(st, nxt.y);
            if (lane == 0)          // 1-wavefront predicated STG.128
                *(float4*)(gd + g * 16) = sp;

            cur = nxt;
            nxt = nn;
        }
        s0 = s1;
    }
}

extern "C" void kernel_launch(void* const* d_in, const int* in_sizes, int n_in,
                              void* d_out, int out_size) {
    (void)in_sizes; (void)n_in; (void)out_size;
    const float* x = (const float*)d_in[0];
    float* out     = (float*)d_out;

    // 128 blocks x 4 self-sufficient warps (1 sequence each). No barriers,
    // no I/O warp: all 4 SMSPs run identical compute-only streams.
    DeltaModulationEncoder_kernel<<<NSEQ / WARPS, WARPS * 32>>>(x, out);
}